// round 15
// baseline (speedup 1.0000x reference)
#include <cuda_runtime.h>
#include <cuda_fp16.h>
#include <cuda_bf16.h>

#define NMAX 100000
#define NPAD 100096         // NMAX rounded up to 128 (branch-free gemm tiles)
#define EMAX 3200000
#define K_IN 116
#define KPH  128            // K padded to 128 for fp16 mma (k16 steps)
#define H_OUT 256
#define SCAN_B 256
#define XH_W 128            // padded fp16 row width (256B, aligned); elem 116 = dinv
#define AH_STRIDE 136       // Xs smem row stride in halves (conflict-free A frags)
#define WN_STRIDE 264       // Ws smem row stride in half2/uint (conflict-free B frags)
#define GEMM_ROWS 128
#define GEMM_BLOCKS 148

// Scratch (static device globals: allocation-free per harness rules)
__device__ int    g_deg[NMAX];
__device__ int    g_cursor[NMAX];
__device__ int    g_rowptr[NMAX + 1];
__device__ int    g_col[EMAX];
__device__ __half g_aggh[(size_t)NPAD * KPH];   // fp16 aggregate (zero-init)
__device__ __half g_xh[(size_t)NMAX * XH_W];
__device__ int    g_bsum[(NMAX + SCAN_B - 1) / SCAN_B];

// ---------------------------------------------------------------------------
__global__ void count_kernel(const int* __restrict__ dst, int e) {
    int i = (blockIdx.x * blockDim.x + threadIdx.x) * 4;
    if (i + 3 < e) {
        int4 d4 = *(const int4*)&dst[i];
        atomicAdd(&g_deg[d4.x], 1);
        atomicAdd(&g_deg[d4.y], 1);
        atomicAdd(&g_deg[d4.z], 1);
        atomicAdd(&g_deg[d4.w], 1);
    } else {
        for (; i < e; i++) atomicAdd(&g_deg[dst[i]], 1);
    }
}

// convert (NO degree dependency): g_xh[i][c] = half(x[i][c]), unscaled.
// Elements 116..117 are owned by scanC's dinv patch; convert writes 118..127
// pad zeros only (disjoint 4B words -> no race with the patch).
__global__ void convert_kernel(const float* __restrict__ x, int n) {
    int i = blockIdx.x * blockDim.x + threadIdx.x;   // n*32 threads
    int node = i >> 5;
    int c4 = (i & 31) * 4;
    if (node >= n) return;
    if (c4 + 4 <= K_IN) {                 // lanes 0..28
        float4 v = *(const float4*)&x[(size_t)node * K_IN + c4];
        __half2 h0 = __floats2half2_rn(v.x, v.y);
        __half2 h1 = __floats2half2_rn(v.z, v.w);
        uint2 u;
        u.x = *(unsigned int*)&h0;
        u.y = *(unsigned int*)&h1;
        *(uint2*)&g_xh[(size_t)node * XH_W + c4] = u;
    } else if (c4 == 116) {               // lane 29: zero elements 118,119 only
        *(unsigned int*)&g_xh[(size_t)node * XH_W + 118] = 0u;
    } else {                              // lanes 30,31: zero 120..127
        uint2 z; z.x = 0u; z.y = 0u;
        *(uint2*)&g_xh[(size_t)node * XH_W + c4] = z;
    }
}

// --- 2-phase scan ---------------------------------------------------------
__global__ void scanA_kernel(int n) {
    __shared__ int s[SCAN_B];
    int g = blockIdx.x * SCAN_B + threadIdx.x;
    s[threadIdx.x] = (g < n) ? g_deg[g] : 0;
    __syncthreads();
    for (int off = SCAN_B / 2; off > 0; off >>= 1) {
        if (threadIdx.x < off) s[threadIdx.x] += s[threadIdx.x + off];
        __syncthreads();
    }
    if (threadIdx.x == 0) g_bsum[blockIdx.x] = s[0];
}

// scanC: block-offset reduce inline + local exclusive scan; publish rowptr +
// cursor; ALSO patch half(dinv) into element 116 of this node's xh row.
__global__ void scanC_kernel(int n) {
    __shared__ int red[SCAN_B];
    __shared__ int s[SCAN_B];
    int tid = threadIdx.x;

    int acc = 0;
    for (int j = tid; j < blockIdx.x; j += SCAN_B) acc += g_bsum[j];
    red[tid] = acc;
    __syncthreads();
    for (int off = SCAN_B / 2; off > 0; off >>= 1) {
        if (tid < off) red[tid] += red[tid + off];
        __syncthreads();
    }
    int base = red[0];

    int g = blockIdx.x * SCAN_B + tid;
    int d = (g < n) ? g_deg[g] : 0;
    s[tid] = d;
    __syncthreads();
    for (int off = 1; off < SCAN_B; off <<= 1) {
        int t = (tid >= off) ? s[tid - off] : 0;
        __syncthreads();
        s[tid] += t;
        __syncthreads();
    }
    int incl = s[tid];
    if (g < n) {
        int excl = base + incl - d;
        g_rowptr[g] = excl;
        g_cursor[g] = excl;
        __half dh = __float2half_rn(rsqrtf((float)(d + 1)));
        *(unsigned int*)&g_xh[(size_t)g * XH_W + 116] =
            (unsigned int)__half_as_ushort(dh);   // {dinv, 0}
    }
    if (g == n - 1) g_rowptr[n] = base + incl;
}

// --- bucket fill: cursor pre-seeded with rowptr, packed CSR ---------------
__global__ void fill_kernel(const int* __restrict__ src,
                            const int* __restrict__ dst, int e) {
    int i = (blockIdx.x * blockDim.x + threadIdx.x) * 4;
    if (i + 3 < e) {
        int4 d4 = *(const int4*)&dst[i];
        int4 s4 = *(const int4*)&src[i];
        g_col[atomicAdd(&g_cursor[d4.x], 1)] = s4.x;
        g_col[atomicAdd(&g_cursor[d4.y], 1)] = s4.y;
        g_col[atomicAdd(&g_cursor[d4.z], 1)] = s4.z;
        g_col[atomicAdd(&g_cursor[d4.w], 1)] = s4.w;
    } else {
        for (; i < e; i++)
            g_col[atomicAdd(&g_cursor[dst[i]], 1)] = src[i];
    }
}

// --- pull aggregation -----------------------------------------------------
// Rows are UNSCALED; each row carries half(dinv) at element 116 (lane 29's
// low half). Per edge: SHFL-broadcast dinv, HMUL2-scale, then HADD2 trees.
__device__ __forceinline__ void scale_edge(uint2 u, __half2& ox, __half2& oy) {
    unsigned int dv = __shfl_sync(0xffffffffu, u.x, 29);
    __half2 dv2 = __half2half2(__ushort_as_half((unsigned short)(dv & 0xffffu)));
    ox = __hmul2(*(__half2*)&u.x, dv2);
    oy = __hmul2(*(__half2*)&u.y, dv2);
}

__global__ void agg_kernel(int n) {
    int gwarp = (blockIdx.x * blockDim.x + threadIdx.x) >> 5;
    int lane  = threadIdx.x & 31;
    if (gwarp >= n) return;
    int dst = gwarp;
    float di = rsqrtf((float)(g_deg[dst] + 1));
    const uint2* xr = (const uint2*)g_xh;   // row = 32 uint2 (256 B)

    float4 acc;
    {   // self loop: di * x_d  (final *di makes it di^2 * x_d)
        uint2 u = xr[(size_t)dst * 32 + lane];
        float2 f0 = __half22float2(*(__half2*)&u.x);
        float2 f1 = __half22float2(*(__half2*)&u.y);
        acc.x = f0.x * di; acc.y = f0.y * di;
        acc.z = f1.x * di; acc.w = f1.y * di;
    }
    int e   = g_rowptr[dst];
    int end = g_rowptr[dst + 1];

    for (; e + 16 <= end; e += 16) {
        uint2 u[16];
        #pragma unroll
        for (int q = 0; q < 16; q++) {
            int s = g_col[e + q];
            u[q] = xr[(size_t)s * 32 + lane];
        }
        __half2 sx[16], sy[16];
        #pragma unroll
        for (int q = 0; q < 16; q++) scale_edge(u[q], sx[q], sy[q]);

        __half2 ax = __hadd2(__hadd2(sx[0], sx[1]), __hadd2(sx[2], sx[3]));
        __half2 ay = __hadd2(__hadd2(sy[0], sy[1]), __hadd2(sy[2], sy[3]));
        __half2 bx = __hadd2(__hadd2(sx[4], sx[5]), __hadd2(sx[6], sx[7]));
        __half2 by = __hadd2(__hadd2(sy[4], sy[5]), __hadd2(sy[6], sy[7]));
        __half2 cx = __hadd2(__hadd2(sx[8], sx[9]), __hadd2(sx[10], sx[11]));
        __half2 cy = __hadd2(__hadd2(sy[8], sy[9]), __hadd2(sy[10], sy[11]));
        __half2 dx = __hadd2(__hadd2(sx[12], sx[13]), __hadd2(sx[14], sx[15]));
        __half2 dy = __hadd2(__hadd2(sy[12], sy[13]), __hadd2(sy[14], sy[15]));
        float2 f0 = __half22float2(ax), f1 = __half22float2(ay);
        float2 f2 = __half22float2(bx), f3 = __half22float2(by);
        float2 f4 = __half22float2(cx), f5 = __half22float2(cy);
        float2 f6 = __half22float2(dx), f7 = __half22float2(dy);
        acc.x += (f0.x + f2.x) + (f4.x + f6.x);
        acc.y += (f0.y + f2.y) + (f4.y + f6.y);
        acc.z += (f1.x + f3.x) + (f5.x + f7.x);
        acc.w += (f1.y + f3.y) + (f5.y + f7.y);
    }
    for (; e + 4 <= end; e += 4) {
        uint2 u0 = xr[(size_t)g_col[e]     * 32 + lane];
        uint2 u1 = xr[(size_t)g_col[e + 1] * 32 + lane];
        uint2 u2 = xr[(size_t)g_col[e + 2] * 32 + lane];
        uint2 u3 = xr[(size_t)g_col[e + 3] * 32 + lane];
        __half2 s0x, s0y, s1x, s1y, s2x, s2y, s3x, s3y;
        scale_edge(u0, s0x, s0y);
        scale_edge(u1, s1x, s1y);
        scale_edge(u2, s2x, s2y);
        scale_edge(u3, s3x, s3y);
        __half2 ax = __hadd2(__hadd2(s0x, s1x), __hadd2(s2x, s3x));
        __half2 ay = __hadd2(__hadd2(s0y, s1y), __hadd2(s2y, s3y));
        float2 f0 = __half22float2(ax), f1 = __half22float2(ay);
        acc.x += f0.x; acc.y += f0.y; acc.z += f1.x; acc.w += f1.y;
    }
    for (; e < end; e++) {
        uint2 u = xr[(size_t)g_col[e] * 32 + lane];
        __half2 sx, sy;
        scale_edge(u, sx, sy);
        float2 f0 = __half22float2(sx);
        float2 f1 = __half22float2(sy);
        acc.x += f0.x; acc.y += f0.y; acc.z += f1.x; acc.w += f1.y;
    }
    uint2 o;
    if (lane < 29) {
        __half2 h0 = __floats2half2_rn(acc.x * di, acc.y * di);
        __half2 h1 = __floats2half2_rn(acc.z * di, acc.w * di);
        o.x = *(unsigned int*)&h0;
        o.y = *(unsigned int*)&h1;
    } else {
        o.x = 0u; o.y = 0u;
    }
    *(uint2*)&g_aggh[(size_t)dst * KPH + lane * 4] = o;
}

// --- GEMM: out = relu(agg @ W + b), fp16 mma, persistent, cp.async dbuf ---
__device__ __forceinline__ void cp_async16(void* smem_dst, const void* gsrc) {
    unsigned int sa = (unsigned int)__cvta_generic_to_shared(smem_dst);
    asm volatile("cp.async.ca.shared.global [%0], [%1], 16;" :: "r"(sa), "l"(gsrc));
}

__global__ __launch_bounds__(256, 1) void gemm_kernel(const float* __restrict__ W,
                                                      const float* __restrict__ b,
                                                      float* __restrict__ out,
                                                      int n, int ntiles) {
    extern __shared__ float sh[];
    unsigned int* Ws = (unsigned int*)sh;                          // 64 * 264 uints
    __half* Xs0 = (__half*)(Ws + (KPH / 2) * WN_STRIDE);           // 128 * 136
    __half* Xs1 = Xs0 + GEMM_ROWS * AH_STRIDE;
    float*  bs  = (float*)(Xs1 + GEMM_ROWS * AH_STRIDE);
    int tid = threadIdx.x;
    int wid = tid >> 5, lane = tid & 31;

    int t0 = blockIdx.x;
    if (t0 < ntiles) {
        const uint4* Ag = (const uint4*)(g_aggh + (size_t)t0 * GEMM_ROWS * KPH);
        #pragma unroll
        for (int q = 0; q < 8; q++) {
            int i = tid + q * 256;
            int r = i >> 4, c = i & 15;
            cp_async16((uint4*)Xs0 + r * 17 + c, Ag + i);
        }
        asm volatile("cp.async.commit_group;");
    }
    for (int i = tid; i < (KPH / 2) * H_OUT; i += 256) {
        int k2 = i >> 8, nn = i & 255;
        int k0 = 2 * k2, k1 = 2 * k2 + 1;
        float v0 = (k0 < K_IN) ? W[k0 * H_OUT + nn] : 0.f;
        float v1 = (k1 < K_IN) ? W[k1 * H_OUT + nn] : 0.f;
        __half2 h = __floats2half2_rn(v0, v1);
        Ws[(i >> 8) * WN_STRIDE + (i & 255)] = *(unsigned int*)&h;
    }
    bs[tid] = b[tid];

    int tg = lane >> 2, tr = lane & 3;
    int wr = wid >> 2;
    int wc = wid & 3;
    int buf = 0;

    for (int t = blockIdx.x; t < ntiles; t += GEMM_BLOCKS) {
        asm volatile("cp.async.wait_group 0;");
        __syncthreads();

        __half* Xc = buf ? Xs1 : Xs0;
        __half* Xn = buf ? Xs0 : Xs1;

        int tn = t + GEMM_BLOCKS;
        if (tn < ntiles) {
            const uint4* Ag = (const uint4*)(g_aggh + (size_t)tn * GEMM_ROWS * KPH);
            #pragma unroll
            for (int q = 0; q < 8; q++) {
                int i = tid + q * 256;
                int r = i >> 4, c = i & 15;
                cp_async16((uint4*)Xn + r * 17 + c, Ag + i);
            }
            asm volatile("cp.async.commit_group;");
        }

        float d[4][8][4];
        #pragma unroll
        for (int m = 0; m < 4; m++)
            #pragma unroll
            for (int j = 0; j < 8; j++)
                #pragma unroll
                for (int q = 0; q < 4; q++) d[m][j][q] = 0.f;

        int row0 = t * GEMM_ROWS;

        #pragma unroll
        for (int ks = 0; ks < KPH / 16; ks++) {
            int k0 = ks * 16;
            unsigned int am[4][4];
            #pragma unroll
            for (int m = 0; m < 4; m++) {
                const __half* Xr = Xc + (wr * 64 + m * 16 + tg) * AH_STRIDE;
                am[m][0] = *(const unsigned int*)&Xr[k0 + 2 * tr];
                am[m][1] = *(const unsigned int*)&Xr[8 * AH_STRIDE + k0 + 2 * tr];
                am[m][2] = *(const unsigned int*)&Xr[k0 + 2 * tr + 8];
                am[m][3] = *(const unsigned int*)&Xr[8 * AH_STRIDE + k0 + 2 * tr + 8];
            }
            unsigned int bb[8][2];
            const unsigned int* Wb0 = Ws + (k0 / 2 + tr) * WN_STRIDE + wc * 64 + tg;
            const unsigned int* Wb1 = Wb0 + 4 * WN_STRIDE;
            #pragma unroll
            for (int j = 0; j < 8; j++) {
                bb[j][0] = Wb0[j * 8];
                bb[j][1] = Wb1[j * 8];
            }
            #pragma unroll
            for (int m = 0; m < 4; m++)
                #pragma unroll
                for (int j = 0; j < 8; j++)
                    asm("mma.sync.aligned.m16n8k16.row.col.f32.f16.f16.f32 "
                        "{%0,%1,%2,%3}, {%4,%5,%6,%7}, {%8,%9}, {%0,%1,%2,%3};"
                        : "+f"(d[m][j][0]), "+f"(d[m][j][1]),
                          "+f"(d[m][j][2]), "+f"(d[m][j][3])
                        : "r"(am[m][0]), "r"(am[m][1]), "r"(am[m][2]), "r"(am[m][3]),
                          "r"(bb[j][0]), "r"(bb[j][1]));
        }

        #pragma unroll
        for (int m = 0; m < 4; m++) {
            int rA = row0 + wr * 64 + m * 16 + tg;
            int rB = rA + 8;
            #pragma unroll
            for (int j = 0; j < 8; j++) {
                int col = wc * 64 + j * 8 + 2 * tr;
                float bx = bs[col], by = bs[col + 1];
                if (rA < n) {
                    float2 o;
                    o.x = fmaxf(d[m][j][0] + bx, 0.f);
                    o.y = fmaxf(d[m][j][1] + by, 0.f);
                    *(float2*)&out[(size_t)rA * H_OUT + col] = o;
                }
                if (rB < n) {
                    float2 o;
                    o.x = fmaxf(d[m][j][2] + bx, 0.f);
                    o.y = fmaxf(d[m][j][3] + by, 0.f);
                    *(float2*)&out[(size_t)rB * H_OUT + col] = o;
                }
            }
        }
        buf ^= 1;
    }
}

// ---------------------------------------------------------------------------
extern "C" void kernel_launch(void* const* d_in, const int* in_sizes, int n_in,
                              void* d_out, int out_size) {
    const float* x  = (const float*)d_in[0];
    const int*   ei = (const int*)d_in[1];
    const float* W  = (const float*)d_in[2];
    const float* b  = (const float*)d_in[3];
    float* out = (float*)d_out;

    int n = in_sizes[0] / K_IN;     // 100000
    int e = in_sizes[1] / 2;        // 3200000
    const int* src = ei;
    const int* dst = ei + e;

    // one-time stream/event objects (identical captured work every call)
    static cudaStream_t s2 = nullptr;
    static cudaEvent_t evF, evX;
    if (!s2) {
        cudaStreamCreateWithFlags(&s2, cudaStreamNonBlocking);
        cudaEventCreateWithFlags(&evF, cudaEventDisableTiming);
        cudaEventCreateWithFlags(&evX, cudaEventDisableTiming);
    }

    int nb_e4 = (e / 4 + 255) / 256;
    int nb_s = (n + SCAN_B - 1) / SCAN_B;

    // fork: convert (no dependencies) runs beside the whole CSR-build chain
    cudaEventRecord(evF, 0);
    cudaStreamWaitEvent(s2, evF, 0);
    convert_kernel<<<(n * 32 + 255) / 256, 256, 0, s2>>>(x, n);
    cudaEventRecord(evX, s2);

    void* p_deg = nullptr;  cudaGetSymbolAddress(&p_deg, g_deg);
    cudaMemsetAsync(p_deg, 0, (size_t)n * sizeof(int));
    count_kernel<<<nb_e4, 256>>>(dst, e);
    scanA_kernel<<<nb_s, SCAN_B>>>(n);
    scanC_kernel<<<nb_s, SCAN_B>>>(n);   // also patches dinv into xh rows
    fill_kernel<<<nb_e4, 256>>>(src, dst, e);

    cudaStreamWaitEvent(0, evX, 0);      // join: agg needs convert done
    int nb_agg = (n * 32 + 255) / 256;
    agg_kernel<<<nb_agg, 256>>>(n);

    int ntiles = (NPAD + GEMM_ROWS - 1) / GEMM_ROWS;   // 782
    int smem = (KPH / 2) * WN_STRIDE * 4 + 2 * GEMM_ROWS * AH_STRIDE * 2 + H_OUT * 4;
    cudaFuncSetAttribute(gemm_kernel, cudaFuncAttributeMaxDynamicSharedMemorySize, smem);
    gemm_kernel<<<GEMM_BLOCKS, 256, smem>>>(W, b, out, n, ntiles);
}

// round 16
// speedup vs baseline: 1.1143x; 1.1143x over previous
#include <cuda_runtime.h>
#include <cuda_fp16.h>
#include <cuda_bf16.h>

#define NMAX 100000
#define NPAD 100096         // NMAX rounded up to 128 (branch-free gemm tiles)
#define EMAX 3200000
#define K_IN 116
#define KPH  128            // K padded to 128 for fp16 mma (k16 steps)
#define H_OUT 256
#define SCAN_B 256
#define XH_W 128            // padded fp16 row width (256B, aligned)
#define AH_STRIDE 136       // Xs smem row stride in halves (conflict-free A frags)
#define WN_STRIDE 264       // Ws smem row stride in half2/uint (conflict-free B frags)
#define GEMM_ROWS 128
#define GEMM_BLOCKS 148

// Scratch (static device globals: allocation-free per harness rules)
__device__ int    g_deg[NMAX];
__device__ int    g_cursor[NMAX];
__device__ int    g_rowptr[NMAX + 1];
__device__ int    g_col[EMAX];
__device__ __half g_aggh[(size_t)NPAD * KPH];   // fp16 aggregate (zero-init)
__device__ __half g_xh[(size_t)NMAX * XH_W];
__device__ int    g_bsum[(NMAX + SCAN_B - 1) / SCAN_B];

// ---------------------------------------------------------------------------
__global__ void count_kernel(const int* __restrict__ dst, int e) {
    int i = (blockIdx.x * blockDim.x + threadIdx.x) * 4;
    if (i + 3 < e) {
        int4 d4 = *(const int4*)&dst[i];
        atomicAdd(&g_deg[d4.x], 1);
        atomicAdd(&g_deg[d4.y], 1);
        atomicAdd(&g_deg[d4.z], 1);
        atomicAdd(&g_deg[d4.w], 1);
    } else {
        for (; i < e; i++) atomicAdd(&g_deg[dst[i]], 1);
    }
}

// convert: g_xh[i][c] = half(dinv[i] * x[i][c]), zero-padded to 128 cols
__global__ void convert_kernel(const float* __restrict__ x, int n) {
    int i = blockIdx.x * blockDim.x + threadIdx.x;   // n*32 threads
    int node = i >> 5;
    int c4 = (i & 31) * 4;
    if (node >= n) return;
    float di = rsqrtf((float)(g_deg[node] + 1));
    __half2 h0, h1;
    if (c4 < K_IN) {
        float4 v = *(const float4*)&x[(size_t)node * K_IN + c4];
        h0 = __floats2half2_rn(v.x * di, v.y * di);
        h1 = __floats2half2_rn(v.z * di, v.w * di);
    } else {
        h0 = __floats2half2_rn(0.f, 0.f);
        h1 = h0;
    }
    uint2 u;
    u.x = *(unsigned int*)&h0;
    u.y = *(unsigned int*)&h1;
    *(uint2*)&g_xh[(size_t)node * XH_W + c4] = u;
}

// --- 2-phase scan ---------------------------------------------------------
__global__ void scanA_kernel(int n) {
    __shared__ int s[SCAN_B];
    int g = blockIdx.x * SCAN_B + threadIdx.x;
    s[threadIdx.x] = (g < n) ? g_deg[g] : 0;
    __syncthreads();
    for (int off = SCAN_B / 2; off > 0; off >>= 1) {
        if (threadIdx.x < off) s[threadIdx.x] += s[threadIdx.x + off];
        __syncthreads();
    }
    if (threadIdx.x == 0) g_bsum[blockIdx.x] = s[0];
}

// scanC: block-offset reduce inline + local exclusive scan; publish to BOTH
// rowptr and cursor (fill atomics on cursor).
__global__ void scanC_kernel(int n) {
    __shared__ int red[SCAN_B];
    __shared__ int s[SCAN_B];
    int tid = threadIdx.x;

    int acc = 0;
    for (int j = tid; j < blockIdx.x; j += SCAN_B) acc += g_bsum[j];
    red[tid] = acc;
    __syncthreads();
    for (int off = SCAN_B / 2; off > 0; off >>= 1) {
        if (tid < off) red[tid] += red[tid + off];
        __syncthreads();
    }
    int base = red[0];

    int g = blockIdx.x * SCAN_B + tid;
    int d = (g < n) ? g_deg[g] : 0;
    s[tid] = d;
    __syncthreads();
    for (int off = 1; off < SCAN_B; off <<= 1) {
        int t = (tid >= off) ? s[tid - off] : 0;
        __syncthreads();
        s[tid] += t;
        __syncthreads();
    }
    int incl = s[tid];
    if (g < n) {
        int excl = base + incl - d;
        g_rowptr[g] = excl;
        g_cursor[g] = excl;
    }
    if (g == n - 1) g_rowptr[n] = base + incl;
}

// --- bucket fill: cursor pre-seeded with rowptr, packed CSR ---------------
__global__ void fill_kernel(const int* __restrict__ src,
                            const int* __restrict__ dst, int e) {
    int i = (blockIdx.x * blockDim.x + threadIdx.x) * 4;
    if (i + 3 < e) {
        int4 d4 = *(const int4*)&dst[i];
        int4 s4 = *(const int4*)&src[i];
        g_col[atomicAdd(&g_cursor[d4.x], 1)] = s4.x;
        g_col[atomicAdd(&g_cursor[d4.y], 1)] = s4.y;
        g_col[atomicAdd(&g_cursor[d4.z], 1)] = s4.z;
        g_col[atomicAdd(&g_cursor[d4.w], 1)] = s4.w;
    } else {
        for (; i < e; i++)
            g_col[atomicAdd(&g_cursor[dst[i]], 1)] = src[i];
    }
}

// --- pull aggregation: warp/node, fp16 gathers, HADD2 trees, 16x unroll ---
__global__ void agg_kernel(int n) {
    int gwarp = (blockIdx.x * blockDim.x + threadIdx.x) >> 5;
    int lane  = threadIdx.x & 31;
    if (gwarp >= n) return;
    int dst = gwarp;
    float di = rsqrtf((float)(g_deg[dst] + 1));
    const uint2* xr = (const uint2*)g_xh;   // row = 32 uint2 (256 B)

    float4 acc;
    {
        uint2 u = xr[(size_t)dst * 32 + lane];
        float2 f0 = __half22float2(*(__half2*)&u.x);
        float2 f1 = __half22float2(*(__half2*)&u.y);
        acc.x = f0.x; acc.y = f0.y; acc.z = f1.x; acc.w = f1.y;
    }
    int e   = g_rowptr[dst];
    int end = g_rowptr[dst + 1];

    for (; e + 16 <= end; e += 16) {
        uint2 u[16];
        #pragma unroll
        for (int q = 0; q < 16; q++) {
            int s = g_col[e + q];
            u[q] = xr[(size_t)s * 32 + lane];
        }
        __half2 ax = __hadd2(__hadd2(*(__half2*)&u[0].x, *(__half2*)&u[1].x),
                             __hadd2(*(__half2*)&u[2].x, *(__half2*)&u[3].x));
        __half2 ay = __hadd2(__hadd2(*(__half2*)&u[0].y, *(__half2*)&u[1].y),
                             __hadd2(*(__half2*)&u[2].y, *(__half2*)&u[3].y));
        __half2 bx = __hadd2(__hadd2(*(__half2*)&u[4].x, *(__half2*)&u[5].x),
                             __hadd2(*(__half2*)&u[6].x, *(__half2*)&u[7].x));
        __half2 by = __hadd2(__hadd2(*(__half2*)&u[4].y, *(__half2*)&u[5].y),
                             __hadd2(*(__half2*)&u[6].y, *(__half2*)&u[7].y));
        __half2 cx = __hadd2(__hadd2(*(__half2*)&u[8].x, *(__half2*)&u[9].x),
                             __hadd2(*(__half2*)&u[10].x, *(__half2*)&u[11].x));
        __half2 cy = __hadd2(__hadd2(*(__half2*)&u[8].y, *(__half2*)&u[9].y),
                             __hadd2(*(__half2*)&u[10].y, *(__half2*)&u[11].y));
        __half2 dx = __hadd2(__hadd2(*(__half2*)&u[12].x, *(__half2*)&u[13].x),
                             __hadd2(*(__half2*)&u[14].x, *(__half2*)&u[15].x));
        __half2 dy = __hadd2(__hadd2(*(__half2*)&u[12].y, *(__half2*)&u[13].y),
                             __hadd2(*(__half2*)&u[14].y, *(__half2*)&u[15].y));
        float2 f0 = __half22float2(ax), f1 = __half22float2(ay);
        float2 f2 = __half22float2(bx), f3 = __half22float2(by);
        float2 f4 = __half22float2(cx), f5 = __half22float2(cy);
        float2 f6 = __half22float2(dx), f7 = __half22float2(dy);
        acc.x += (f0.x + f2.x) + (f4.x + f6.x);
        acc.y += (f0.y + f2.y) + (f4.y + f6.y);
        acc.z += (f1.x + f3.x) + (f5.x + f7.x);
        acc.w += (f1.y + f3.y) + (f5.y + f7.y);
    }
    for (; e + 4 <= end; e += 4) {
        int s0 = g_col[e], s1 = g_col[e+1], s2 = g_col[e+2], s3 = g_col[e+3];
        uint2 u0 = xr[(size_t)s0 * 32 + lane];
        uint2 u1 = xr[(size_t)s1 * 32 + lane];
        uint2 u2 = xr[(size_t)s2 * 32 + lane];
        uint2 u3 = xr[(size_t)s3 * 32 + lane];
        __half2 ax = __hadd2(__hadd2(*(__half2*)&u0.x, *(__half2*)&u1.x),
                             __hadd2(*(__half2*)&u2.x, *(__half2*)&u3.x));
        __half2 ay = __hadd2(__hadd2(*(__half2*)&u0.y, *(__half2*)&u1.y),
                             __hadd2(*(__half2*)&u2.y, *(__half2*)&u3.y));
        float2 f0 = __half22float2(ax), f1 = __half22float2(ay);
        acc.x += f0.x; acc.y += f0.y; acc.z += f1.x; acc.w += f1.y;
    }
    for (; e < end; e++) {
        int s = g_col[e];
        uint2 u = xr[(size_t)s * 32 + lane];
        float2 f0 = __half22float2(*(__half2*)&u.x);
        float2 f1 = __half22float2(*(__half2*)&u.y);
        acc.x += f0.x; acc.y += f0.y; acc.z += f1.x; acc.w += f1.y;
    }
    uint2 o;
    if (lane < 29) {
        __half2 h0 = __floats2half2_rn(acc.x * di, acc.y * di);
        __half2 h1 = __floats2half2_rn(acc.z * di, acc.w * di);
        o.x = *(unsigned int*)&h0;
        o.y = *(unsigned int*)&h1;
    } else {
        o.x = 0u; o.y = 0u;
    }
    *(uint2*)&g_aggh[(size_t)dst * KPH + lane * 4] = o;
}

// --- GEMM: out = relu(agg @ W + b), fp16 mma, persistent, cp.async dbuf ---
__device__ __forceinline__ void cp_async16(void* smem_dst, const void* gsrc) {
    unsigned int sa = (unsigned int)__cvta_generic_to_shared(smem_dst);
    asm volatile("cp.async.ca.shared.global [%0], [%1], 16;" :: "r"(sa), "l"(gsrc));
}

__global__ __launch_bounds__(256, 1) void gemm_kernel(const float* __restrict__ W,
                                                      const float* __restrict__ b,
                                                      float* __restrict__ out,
                                                      int n, int ntiles) {
    extern __shared__ float sh[];
    unsigned int* Ws = (unsigned int*)sh;                          // 64 * 264 uints
    __half* Xs0 = (__half*)(Ws + (KPH / 2) * WN_STRIDE);           // 128 * 136
    __half* Xs1 = Xs0 + GEMM_ROWS * AH_STRIDE;
    float*  bs  = (float*)(Xs1 + GEMM_ROWS * AH_STRIDE);
    int tid = threadIdx.x;
    int wid = tid >> 5, lane = tid & 31;

    int t0 = blockIdx.x;
    if (t0 < ntiles) {
        const uint4* Ag = (const uint4*)(g_aggh + (size_t)t0 * GEMM_ROWS * KPH);
        #pragma unroll
        for (int q = 0; q < 8; q++) {
            int i = tid + q * 256;
            int r = i >> 4, c = i & 15;
            cp_async16((uint4*)Xs0 + r * 17 + c, Ag + i);
        }
        asm volatile("cp.async.commit_group;");
    }
    for (int i = tid; i < (KPH / 2) * H_OUT; i += 256) {
        int k2 = i >> 8, nn = i & 255;
        int k0 = 2 * k2, k1 = 2 * k2 + 1;
        float v0 = (k0 < K_IN) ? W[k0 * H_OUT + nn] : 0.f;
        float v1 = (k1 < K_IN) ? W[k1 * H_OUT + nn] : 0.f;
        __half2 h = __floats2half2_rn(v0, v1);
        Ws[(i >> 8) * WN_STRIDE + (i & 255)] = *(unsigned int*)&h;
    }
    bs[tid] = b[tid];

    int tg = lane >> 2, tr = lane & 3;
    int wr = wid >> 2;            // 0..1  -> rows wr*64 .. wr*64+63
    int wc = wid & 3;             // 0..3  -> cols wc*64 .. wc*64+63
    int buf = 0;

    for (int t = blockIdx.x; t < ntiles; t += GEMM_BLOCKS) {
        asm volatile("cp.async.wait_group 0;");
        __syncthreads();

        __half* Xc = buf ? Xs1 : Xs0;
        __half* Xn = buf ? Xs0 : Xs1;

        int tn = t + GEMM_BLOCKS;
        if (tn < ntiles) {
            const uint4* Ag = (const uint4*)(g_aggh + (size_t)tn * GEMM_ROWS * KPH);
            #pragma unroll
            for (int q = 0; q < 8; q++) {
                int i = tid + q * 256;
                int r = i >> 4, c = i & 15;
                cp_async16((uint4*)Xn + r * 17 + c, Ag + i);
            }
            asm volatile("cp.async.commit_group;");
        }

        float d[4][8][4];
        #pragma unroll
        for (int m = 0; m < 4; m++)
            #pragma unroll
            for (int j = 0; j < 8; j++)
                #pragma unroll
                for (int q = 0; q < 4; q++) d[m][j][q] = 0.f;

        int row0 = t * GEMM_ROWS;

        #pragma unroll
        for (int ks = 0; ks < KPH / 16; ks++) {
            int k0 = ks * 16;
            unsigned int am[4][4];
            #pragma unroll
            for (int m = 0; m < 4; m++) {
                const __half* Xr = Xc + (wr * 64 + m * 16 + tg) * AH_STRIDE;
                am[m][0] = *(const unsigned int*)&Xr[k0 + 2 * tr];
                am[m][1] = *(const unsigned int*)&Xr[8 * AH_STRIDE + k0 + 2 * tr];
                am[m][2] = *(const unsigned int*)&Xr[k0 + 2 * tr + 8];
                am[m][3] = *(const unsigned int*)&Xr[8 * AH_STRIDE + k0 + 2 * tr + 8];
            }
            unsigned int bb[8][2];
            const unsigned int* Wb0 = Ws + (k0 / 2 + tr) * WN_STRIDE + wc * 64 + tg;
            const unsigned int* Wb1 = Wb0 + 4 * WN_STRIDE;
            #pragma unroll
            for (int j = 0; j < 8; j++) {
                bb[j][0] = Wb0[j * 8];
                bb[j][1] = Wb1[j * 8];
            }
            #pragma unroll
            for (int m = 0; m < 4; m++)
                #pragma unroll
                for (int j = 0; j < 8; j++)
                    asm("mma.sync.aligned.m16n8k16.row.col.f32.f16.f16.f32 "
                        "{%0,%1,%2,%3}, {%4,%5,%6,%7}, {%8,%9}, {%0,%1,%2,%3};"
                        : "+f"(d[m][j][0]), "+f"(d[m][j][1]),
                          "+f"(d[m][j][2]), "+f"(d[m][j][3])
                        : "r"(am[m][0]), "r"(am[m][1]), "r"(am[m][2]), "r"(am[m][3]),
                          "r"(bb[j][0]), "r"(bb[j][1]));
        }

        #pragma unroll
        for (int m = 0; m < 4; m++) {
            int rA = row0 + wr * 64 + m * 16 + tg;
            int rB = rA + 8;
            #pragma unroll
            for (int j = 0; j < 8; j++) {
                int col = wc * 64 + j * 8 + 2 * tr;
                float bx = bs[col], by = bs[col + 1];
                if (rA < n) {
                    float2 o;
                    o.x = fmaxf(d[m][j][0] + bx, 0.f);
                    o.y = fmaxf(d[m][j][1] + by, 0.f);
                    *(float2*)&out[(size_t)rA * H_OUT + col] = o;
                }
                if (rB < n) {
                    float2 o;
                    o.x = fmaxf(d[m][j][2] + bx, 0.f);
                    o.y = fmaxf(d[m][j][3] + by, 0.f);
                    *(float2*)&out[(size_t)rB * H_OUT + col] = o;
                }
            }
        }
        buf ^= 1;
    }
}

// ---------------------------------------------------------------------------
extern "C" void kernel_launch(void* const* d_in, const int* in_sizes, int n_in,
                              void* d_out, int out_size) {
    const float* x  = (const float*)d_in[0];
    const int*   ei = (const int*)d_in[1];
    const float* W  = (const float*)d_in[2];
    const float* b  = (const float*)d_in[3];
    float* out = (float*)d_out;

    int n = in_sizes[0] / K_IN;     // 100000
    int e = in_sizes[1] / 2;        // 3200000
    const int* src = ei;
    const int* dst = ei + e;

    // one-time stream/event objects (identical captured work every call)
    static cudaStream_t s2 = nullptr;
    static cudaEvent_t evC, evX;
    if (!s2) {
        cudaStreamCreateWithFlags(&s2, cudaStreamNonBlocking);
        cudaEventCreateWithFlags(&evC, cudaEventDisableTiming);
        cudaEventCreateWithFlags(&evX, cudaEventDisableTiming);
    }

    int nb_e4 = (e / 4 + 255) / 256;
    int nb_s = (n + SCAN_B - 1) / SCAN_B;

    void* p_deg = nullptr;  cudaGetSymbolAddress(&p_deg, g_deg);
    cudaMemsetAsync(p_deg, 0, (size_t)n * sizeof(int));
    count_kernel<<<nb_e4, 256>>>(dst, e);
    cudaEventRecord(evC, 0);

    // fork: convert (needs only degrees) runs beside scanA/scanC/fill
    cudaStreamWaitEvent(s2, evC, 0);
    convert_kernel<<<(n * 32 + 255) / 256, 256, 0, s2>>>(x, n);
    cudaEventRecord(evX, s2);

    scanA_kernel<<<nb_s, SCAN_B>>>(n);
    scanC_kernel<<<nb_s, SCAN_B>>>(n);
    fill_kernel<<<nb_e4, 256>>>(src, dst, e);

    cudaStreamWaitEvent(0, evX, 0);      // join: agg needs convert done
    int nb_agg = (n * 32 + 255) / 256;
    agg_kernel<<<nb_agg, 256>>>(n);

    int ntiles = (NPAD + GEMM_ROWS - 1) / GEMM_ROWS;   // 782
    int smem = (KPH / 2) * WN_STRIDE * 4 + 2 * GEMM_ROWS * AH_STRIDE * 2 + H_OUT * 4;
    cudaFuncSetAttribute(gemm_kernel, cudaFuncAttributeMaxDynamicSharedMemorySize, smem);
    gemm_kernel<<<GEMM_BLOCKS, 256, smem>>>(W, b, out, n, ntiles);
}